// round 3
// baseline (speedup 1.0000x reference)
#include <cuda_runtime.h>
#include <cuda_fp16.h>
#include <cstdint>
#include <math.h>

// ------------------------------------------------------------------
// Problem constants (fixed by setup_inputs)
// ------------------------------------------------------------------
#define B_Q    128          // number of queries
#define DIM    128          // vector dimension
#define TILE_M 256          // db rows per CTA
#define KVAL   10           // top-k
#define NSEG   8            // top-k segments per query

#define STRIDE_H 136        // halves per SMEM tile row (16B-aligned, conflict-free ldmatrix)
#define STRIDE_S 260        // floats per staging row

// ------------------------------------------------------------------
// Device global scratch (no cudaMalloc allowed)
// ------------------------------------------------------------------
__device__ __align__(16) __half g_qh[B_Q * STRIDE_H];  // Q hi image (stride-136 rows)
__device__ __align__(16) __half g_ql[B_Q * STRIDE_H];  // Q lo image
__device__ float g_qinv[B_Q];
__device__ float g_pv[B_Q * NSEG * KVAL];
__device__ int   g_pi[B_Q * NSEG * KVAL];
// Only used if the output buffer holds indices alone (no room for sims there).
__device__ float g_sims_scratch[(size_t)B_Q * 1000000];

// ------------------------------------------------------------------
// PTX helpers (sm_103-neutral: ldmatrix + mma.sync only)
// ------------------------------------------------------------------
__device__ __forceinline__ uint32_t smem_to_u32(const void* p) {
    uint32_t a;
    asm("{ .reg .u64 t; cvta.to.shared.u64 t, %1; cvt.u32.u64 %0, t; }"
        : "=r"(a) : "l"(p));
    return a;
}

__device__ __forceinline__ void ldsm_x4(uint32_t r[4], uint32_t addr) {
    asm volatile("ldmatrix.sync.aligned.m8n8.x4.shared.b16 {%0,%1,%2,%3}, [%4];"
        : "=r"(r[0]), "=r"(r[1]), "=r"(r[2]), "=r"(r[3]) : "r"(addr));
}

__device__ __forceinline__ void mma16816(float c[4], const uint32_t a[4], const uint32_t b[2]) {
    asm volatile(
        "mma.sync.aligned.m16n8k16.row.col.f32.f16.f16.f32 "
        "{%0,%1,%2,%3}, {%4,%5,%6,%7}, {%8,%9}, {%0,%1,%2,%3};"
        : "+f"(c[0]), "+f"(c[1]), "+f"(c[2]), "+f"(c[3])
        : "r"(a[0]), "r"(a[1]), "r"(a[2]), "r"(a[3]), "r"(b[0]), "r"(b[1]));
}

// ------------------------------------------------------------------
// SMEM layout (dynamic) for the GEMM kernel
// ------------------------------------------------------------------
#define SM_QINV  0                         // float[128]
#define SM_DBINV 512                       // float[256]
#define SM_AH    1536                      // 256 x 136 halves = 69632 B
#define SM_AL    (SM_AH + 69632)
#define SM_BH    (SM_AL + 69632)           // 128 x 136 halves = 34816 B
#define SM_BL    (SM_BH + 34816)
#define SMEM_BYTES (SM_BL + 34816)         // 210432 B

// ------------------------------------------------------------------
// Kernel 1: query prep — inv norms + hi/lo f16 images (stride-136 rows)
// ------------------------------------------------------------------
__global__ void vs_prep_q(const float* __restrict__ q) {
    int t = threadIdx.x;           // one thread per query row
    if (t >= B_Q) return;
    float s = 0.f;
    for (int j = 0; j < DIM; j++) {
        float v = q[t * DIM + j];
        s += v * v;
    }
    g_qinv[t] = 1.f / fmaxf(sqrtf(s), 1e-12f);
    for (int j = 0; j < DIM; j++) {
        float v = q[t * DIM + j];
        __half h = __float2half_rn(v);
        __half l = __float2half_rn(v - __half2float(h));
        g_qh[t * STRIDE_H + j] = h;
        g_ql[t * STRIDE_H + j] = l;
    }
}

// ------------------------------------------------------------------
// Kernel 2: GEMM — one CTA: 256 db rows x 128 queries, K=128,
// 3-pass fp16 split (AhBh + AhBl + AlBh), fp32 accum in registers.
// ------------------------------------------------------------------
__global__ void __launch_bounds__(512, 1)
vs_gemm(const float* __restrict__ db, float* __restrict__ sims, int Nv) {
    extern __shared__ char smem[];
    uint32_t sb = smem_to_u32(smem);
    int tid = threadIdx.x, wid = tid >> 5, lane = tid & 31;
    int n0 = blockIdx.x * TILE_M;

    float* s_qinv  = (float*)(smem + SM_QINV);
    float* s_dbinv = (float*)(smem + SM_DBINV);
    if (tid < B_Q) s_qinv[tid] = g_qinv[tid];

    // Copy pre-built Q hi/lo images (L2-resident, 2 x 34816 B)
    {
        const uint4* qh4 = (const uint4*)g_qh;
        const uint4* ql4 = (const uint4*)g_ql;
        uint4* bh = (uint4*)(smem + SM_BH);
        uint4* bl = (uint4*)(smem + SM_BL);
        for (int i = tid; i < (B_Q * STRIDE_H) / 8; i += 512) {
            bh[i] = qh4[i];
            bl[i] = ql4[i];
        }
    }

    // Load db tile (256 rows x 128 f32), split to f16 hi/lo, row inv-norms.
    // Warp w handles row (w + 16*it); lanes load consecutive float4 -> coalesced.
    {
        const float4* dbv = (const float4*)db;
        #pragma unroll 4
        for (int it = 0; it < 16; it++) {
            int r  = wid + 16 * it;
            int gr = n0 + r;
            float4 v = make_float4(0.f, 0.f, 0.f, 0.f);
            if (gr < Nv) v = dbv[(size_t)gr * 32 + lane];
            float ss = v.x * v.x + v.y * v.y + v.z * v.z + v.w * v.w;
            #pragma unroll
            for (int o = 16; o; o >>= 1) ss += __shfl_xor_sync(0xffffffffu, ss, o);
            if (lane == 0) s_dbinv[r] = 1.f / fmaxf(sqrtf(ss), 1e-12f);

            __half hx = __float2half_rn(v.x), hy = __float2half_rn(v.y);
            __half hz = __float2half_rn(v.z), hw = __float2half_rn(v.w);
            __half lx = __float2half_rn(v.x - __half2float(hx));
            __half ly = __float2half_rn(v.y - __half2float(hy));
            __half lz = __float2half_rn(v.z - __half2float(hz));
            __half lw = __float2half_rn(v.w - __half2float(hw));
            uint32_t off = (uint32_t)(r * STRIDE_H + lane * 4) * 2;
            *(__half2*)(smem + SM_AH + off)     = __halves2half2(hx, hy);
            *(__half2*)(smem + SM_AH + off + 4) = __halves2half2(hz, hw);
            *(__half2*)(smem + SM_AL + off)     = __halves2half2(lx, ly);
            *(__half2*)(smem + SM_AL + off + 4) = __halves2half2(lz, lw);
        }
    }
    __syncthreads();

    // Warp tiling: 8 (m) x 2 (n); each warp owns 32 rows x 64 cols.
    int warp_m = wid & 7, warp_n = wid >> 3;
    int mbase = warp_m * 32, nbase = warp_n * 64;

    float c[2][8][4];
    #pragma unroll
    for (int tm = 0; tm < 2; tm++)
        #pragma unroll
        for (int sub = 0; sub < 8; sub++)
            #pragma unroll
            for (int ci = 0; ci < 4; ci++) c[tm][sub][ci] = 0.f;

    // ldmatrix lane addressing (bytes from smem base of the tile)
    // A 16x16: row = base + lane%16, k-chunk = lane/16 (8 halves)
    uint32_t a_lrow  = (uint32_t)(lane & 15);
    uint32_t a_lchnk = (uint32_t)(lane >> 4) * 16;     // bytes
    // B x4: n = nb + lane%8 + (lane>=16)*8, chunk = (lane>>3)&1
    uint32_t b_ln    = (uint32_t)((lane & 7) + ((lane >> 4) << 3));
    uint32_t b_lchnk = (uint32_t)((lane >> 3) & 1) * 16; // bytes

    const uint32_t AH = sb + SM_AH, AL = sb + SM_AL;
    const uint32_t BH = sb + SM_BH, BL = sb + SM_BL;

    #pragma unroll
    for (int p = 0; p < 3; p++) {
        uint32_t Abase = (p == 2) ? AL : AH;
        uint32_t Bbase = (p == 1) ? BL : BH;
        #pragma unroll
        for (int ks = 0; ks < 8; ks++) {
            uint32_t kbyte = (uint32_t)ks * 32;   // ks*16 halves
            uint32_t a[2][4];
            #pragma unroll
            for (int tm = 0; tm < 2; tm++) {
                uint32_t row = (uint32_t)(mbase + tm * 16) + a_lrow;
                ldsm_x4(a[tm], Abase + row * (STRIDE_H * 2) + kbyte + a_lchnk);
            }
            uint32_t b[8][2];
            #pragma unroll
            for (int g = 0; g < 4; g++) {
                uint32_t n = (uint32_t)(nbase + g * 16) + b_ln;
                uint32_t r[4];
                ldsm_x4(r, Bbase + n * (STRIDE_H * 2) + kbyte + b_lchnk);
                b[g * 2][0] = r[0]; b[g * 2][1] = r[1];
                b[g * 2 + 1][0] = r[2]; b[g * 2 + 1][1] = r[3];
            }
            #pragma unroll
            for (int tm = 0; tm < 2; tm++)
                #pragma unroll
                for (int sub = 0; sub < 8; sub++)
                    mma16816(c[tm][sub], a[tm], b[sub]);
        }
    }
    __syncthreads();   // all mma reads of SMEM done before staging overwrites A

    // Stage scaled results to SMEM as [query][dbrow], then coalesced store.
    float* st = (float*)(smem + SM_AH);   // 128 x 260 floats = 133120 B (fits A hi+lo)
    #pragma unroll
    for (int tm = 0; tm < 2; tm++) {
        int mrow = mbase + tm * 16 + (lane >> 2);
        #pragma unroll
        for (int sub = 0; sub < 8; sub++) {
            int ncol = nbase + sub * 8 + ((lane & 3) << 1);
            #pragma unroll
            for (int ci = 0; ci < 4; ci++) {
                int m = mrow + ((ci >> 1) << 3);
                int n = ncol + (ci & 1);
                st[n * STRIDE_S + m] = c[tm][sub][ci] * s_qinv[n] * s_dbinv[m];
            }
        }
    }
    __syncthreads();

    int limit = min(TILE_M, Nv - n0);     // Nv and tiles are multiples of 4
    for (int i = tid; i < B_Q * (TILE_M / 4); i += 512) {
        int q  = i >> 6;                  // TILE_M/4 = 64 float4 per query row
        int m4 = (i & 63) << 2;
        if (m4 < limit) {
            float4 v = *(float4*)&st[q * STRIDE_S + m4];
            *(float4*)&sims[(size_t)q * (size_t)Nv + n0 + m4] = v;
        }
    }
}

// ------------------------------------------------------------------
// Top-k: strict total order (value desc, index asc) = jax.lax.top_k
// ------------------------------------------------------------------
__device__ __forceinline__ bool vs_better(float v1, int i1, float v2, int i2) {
    return (v1 > v2) || (v1 == v2 && i1 < i2);
}

__device__ __forceinline__ void vs_insert(float* tv, int* ti, float v, int i) {
    if (!vs_better(v, i, tv[0], ti[0])) return;
    int p = 0;
    while (p < KVAL - 1 && vs_better(v, i, tv[p + 1], ti[p + 1])) {
        tv[p] = tv[p + 1]; ti[p] = ti[p + 1]; p++;
    }
    tv[p] = v; ti[p] = i;
}

// Kernel 3: per-(query, segment) partial top-10
__global__ void vs_topk_part(const float* __restrict__ sims, int Nv) {
    __shared__ float sv[256 * KVAL];
    __shared__ int   si[256 * KVAL];
    int q = blockIdx.y, s = blockIdx.x, t = threadIdx.x;
    const float* row = sims + (size_t)q * (size_t)Nv;
    int seg = (Nv + NSEG - 1) / NSEG;
    int st = s * seg;
    int en = min(st + seg, Nv);

    float tv[KVAL]; int ti[KVAL];
    #pragma unroll
    for (int j = 0; j < KVAL; j++) { tv[j] = -3.4e38f; ti[j] = 0x7fffffff; }
    float minv = tv[0]; int mini = ti[0];
    for (int i = st + t; i < en; i += 256) {
        float v = row[i];
        if (vs_better(v, i, minv, mini)) {
            vs_insert(tv, ti, v, i);
            minv = tv[0]; mini = ti[0];
        }
    }
    #pragma unroll
    for (int j = 0; j < KVAL; j++) { sv[t * KVAL + j] = tv[j]; si[t * KVAL + j] = ti[j]; }
    __syncthreads();

    if (t < 32) {
        #pragma unroll
        for (int j = 0; j < KVAL; j++) { tv[j] = -3.4e38f; ti[j] = 0x7fffffff; }
        for (int i = t * 80; i < t * 80 + 80; i++) vs_insert(tv, ti, sv[i], si[i]);
        __syncwarp();
        #pragma unroll
        for (int j = 0; j < KVAL; j++) { sv[t * KVAL + j] = tv[j]; si[t * KVAL + j] = ti[j]; }
        __syncwarp();
        if (t == 0) {
            #pragma unroll
            for (int j = 0; j < KVAL; j++) { tv[j] = -3.4e38f; ti[j] = 0x7fffffff; }
            for (int i = 0; i < 32 * KVAL; i++) vs_insert(tv, ti, sv[i], si[i]);
            int base = (q * NSEG + s) * KVAL;
            for (int j = 0; j < KVAL; j++) { g_pv[base + j] = tv[j]; g_pi[base + j] = ti[j]; }
        }
    }
}

// Kernel 4: merge 8 partials per query, write indices (sorted descending)
__global__ void vs_topk_merge(float* fout, int* iout, int as_int) {
    int q = blockIdx.x;
    if (threadIdx.x != 0) return;
    float bv[NSEG * KVAL]; int bi[NSEG * KVAL];
    int base = q * NSEG * KVAL;
    for (int i = 0; i < NSEG * KVAL; i++) { bv[i] = g_pv[base + i]; bi[i] = g_pi[base + i]; }
    for (int j = 0; j < KVAL; j++) {
        int best = 0;
        for (int i = 1; i < NSEG * KVAL; i++)
            if (vs_better(bv[i], bi[i], bv[best], bi[best])) best = i;
        if (as_int) iout[q * KVAL + j] = bi[best];
        else        fout[q * KVAL + j] = (float)bi[best];
        bv[best] = -3.4e38f; bi[best] = 0x7fffffff;
    }
}

// ------------------------------------------------------------------
// Launch
// ------------------------------------------------------------------
extern "C" void kernel_launch(void* const* d_in, const int* in_sizes, int n_in,
                              void* d_out, int out_size) {
    const float* q  = (const float*)d_in[0];   // vectors     [128, 128]
    const float* db = (const float*)d_in[1];   // db_vectors  [N, 128]
    (void)n_in;
    int Nv = in_sizes[1] / DIM;

    long long BN = (long long)B_Q * (long long)Nv;
    long long BK = (long long)B_Q * KVAL;

    float* sims;
    int mode;                       // 0: [idx(f32), sims] concat; 1: sims only; 2: idx(int32) only
    if ((long long)out_size == BN + BK) { mode = 0; sims = ((float*)d_out) + BK; }
    else if ((long long)out_size == BN) { mode = 1; sims = (float*)d_out; }
    else {
        mode = 2;
        void* p = nullptr;
        cudaGetSymbolAddress(&p, g_sims_scratch);
        sims = (float*)p;
    }

    cudaFuncSetAttribute(vs_gemm, cudaFuncAttributeMaxDynamicSharedMemorySize, SMEM_BYTES);

    vs_prep_q<<<1, 128>>>(q);
    int nblk = (Nv + TILE_M - 1) / TILE_M;
    vs_gemm<<<nblk, 512, SMEM_BYTES>>>(db, sims, Nv);

    if (mode != 1) {
        vs_topk_part<<<dim3(NSEG, B_Q), 256>>>(sims, Nv);
        vs_topk_merge<<<B_Q, 32>>>((float*)d_out, (int*)d_out, mode == 2 ? 1 : 0);
    }
}